// round 4
// baseline (speedup 1.0000x reference)
#include <cuda_runtime.h>
#include <cstdint>

// RecallLoss: input [N=8, C=21, H=512, W=512] f32, target [N, H, W] int64 (or
// int32 — auto-detected). loss = 1 - mean_{n,c} (tp+eps)/(tt+eps).
//
// Single fused kernel. Grid = 1024 blocks; each thread streams TWO float4
// chunks (stride 262144) with no barrier between them so warps de-phase and
// keep LDGs in flight during compute. tp/tt packed into one smem counter.

#define SMOOTH 1e-5f

constexpr int N_IMG  = 8;
constexpr int C_CLS  = 21;
constexpr int HW     = 512 * 512;          // 262144 positions per image
constexpr int HW4    = HW / 4;             // 65536 float4-chunks per image
constexpr int NC     = N_IMG * C_CLS;      // 168 bins
constexpr int TPB    = 256;
constexpr int GRID   = 1024;
constexpr int NTHREADS = GRID * TPB;       // 262144
constexpr int NCHUNK = N_IMG * HW4;        // 524288  (= 2 * NTHREADS)
constexpr int NWARP  = TPB / 32;           // 8

// Zero-initialized at module load; finishing block re-zeroes after each
// launch so every graph replay starts clean.
__device__ int g_tp[NC];
__device__ int g_tt[NC];
__device__ unsigned int g_arrive;

struct SCnt { unsigned int c[NWARP][C_CLS]; };

// One chunk: 21-channel argmax over 4 positions + packed smem count.
__device__ __forceinline__ void do_chunk(
    const float* __restrict__ inp, const void* __restrict__ tgt_raw,
    int is64, int ci, unsigned int (&cnt)[C_CLS])
{
    const int n  = ci >> 16;               // HW4 = 65536
    const long long l0 = (long long)(ci & (HW4 - 1)) * 4;
    const float* base = inp + (long long)n * C_CLS * HW + l0;

    // Channel 0 seeds; strict > keeps first max index (jnp.argmax ties).
    float4 v = __ldcs(reinterpret_cast<const float4*>(base));
    float m0 = v.x, m1 = v.y, m2 = v.z, m3 = v.w;
    int   i0 = 0,  i1 = 0,  i2 = 0,  i3 = 0;

    #pragma unroll
    for (int c = 1; c < C_CLS; c++) {
        float4 u = __ldcs(reinterpret_cast<const float4*>(base + (long long)c * HW));
        if (u.x > m0) { m0 = u.x; i0 = c; }
        if (u.y > m1) { m1 = u.y; i1 = c; }
        if (u.z > m2) { m2 = u.z; i2 = c; }
        if (u.w > m3) { m3 = u.w; i3 = c; }
    }

    int t0, t1, t2, t3;
    if (is64) {
        const long long* tp = (const long long*)tgt_raw + (long long)n * HW + l0;
        longlong2 a = __ldcs(reinterpret_cast<const longlong2*>(tp));
        longlong2 b = __ldcs(reinterpret_cast<const longlong2*>(tp + 2));
        t0 = (int)a.x; t1 = (int)a.y; t2 = (int)b.x; t3 = (int)b.y;
    } else {
        const int* tp = (const int*)tgt_raw + (long long)n * HW + l0;
        int4 a = __ldcs(reinterpret_cast<const int4*>(tp));
        t0 = a.x; t1 = a.y; t2 = a.z; t3 = a.w;
    }

    // cnt[t] layout: bits[15:0] = tt, bits[31:16] = tp (max 1024/warp-class « 64K).
    // NOTE: cnt is a per-(warp,n) shared row selected by caller.
    atomicAdd(&cnt[t0], 1u + (i0 == t0 ? 0x10000u : 0u));
    atomicAdd(&cnt[t1], 1u + (i1 == t1 ? 0x10000u : 0u));
    atomicAdd(&cnt[t2], 1u + (i2 == t2 ? 0x10000u : 0u));
    atomicAdd(&cnt[t3], 1u + (i3 == t3 ? 0x10000u : 0u));
}

__global__ __launch_bounds__(TPB) void recall_fused_kernel(
    const float* __restrict__ inp, const void* __restrict__ tgt_raw,
    float* __restrict__ out)
{
    // Two chunk-iterations per thread can hit two different images n.
    // Keep per-warp counters per image-slot: [NWARP][2][C_CLS] would cost
    // doubling; instead accumulate into per-warp bins indexed by GLOBAL bin
    // (n*C + class) — but that is 168 wide. Compromise: both chunks of a
    // thread use n = ci>>16; chunk1 = chunk0 + NTHREADS, and NTHREADS =
    // 262144 = 4 * HW4, so n1 = n0 + 4 exactly. Two counter rows suffice.
    __shared__ unsigned int s_cnt[2][NWARP][C_CLS];
    __shared__ int s_is64;
    __shared__ float s_red[NWARP];

    const int wid = threadIdx.x >> 5;
    const int lid = threadIdx.x & 31;
    if (lid < C_CLS) { s_cnt[0][wid][lid] = 0; s_cnt[1][wid][lid] = 0; }

    // dtype detect: int64 targets in [0,21) have all-zero odd 32-bit words.
    if (threadIdx.x == 0) {
        const int* w = (const int*)tgt_raw;
        int is64 = 1;
        #pragma unroll
        for (int k = 0; k < 16; k++) is64 &= (w[2 * k + 1] == 0);
        s_is64 = is64;
    }
    __syncthreads();
    const int is64 = s_is64;

    const int gtid = blockIdx.x * TPB + threadIdx.x;
    const int ci0  = gtid;                 // image n0 = gtid >> 16
    const int ci1  = gtid + NTHREADS;      // image n1 = n0 + 4
    static_assert(NTHREADS == 4 * HW4, "chunk1 must land exactly 4 images later");
    static_assert(NCHUNK == 2 * NTHREADS, "two iterations cover all chunks");

    // No barrier between the two chunks: warps de-phase, keeping LDGs in
    // flight while other warps compute.
    do_chunk(inp, tgt_raw, is64, ci0, s_cnt[0][wid]);
    do_chunk(inp, tgt_raw, is64, ci1, s_cnt[1][wid]);

    __syncthreads();

    // Reduce per-warp packed counters -> global bins for the two images this
    // block touched (n0 = all threads share blockIdx: gtid>>16 varies only
    // with block, since TPB*blocks-per-image boundary: HW4/TPB = 256 blocks
    // per image, and blockIdx.x -> n0 = blockIdx.x >> 8).
    const int n0 = blockIdx.x >> 8;        // 256 blocks per image
    const int n1 = n0 + 4;
    if (threadIdx.x < C_CLS) {
        unsigned int a = 0, b = 0;
        #pragma unroll
        for (int w = 0; w < NWARP; w++) { a += s_cnt[0][w][threadIdx.x];
                                          b += s_cnt[1][w][threadIdx.x]; }
        atomicAdd(&g_tt[n0 * C_CLS + threadIdx.x], (int)(a & 0xFFFFu));
        atomicAdd(&g_tp[n0 * C_CLS + threadIdx.x], (int)(a >> 16));
        atomicAdd(&g_tt[n1 * C_CLS + threadIdx.x], (int)(b & 0xFFFFu));
        atomicAdd(&g_tp[n1 * C_CLS + threadIdx.x], (int)(b >> 16));
    }

    // ---- last-block epilogue -------------------------------------------
    __shared__ int s_last;
    __threadfence();   // release this block's counter contributions
    if (threadIdx.x == 0) {
        unsigned int old = atomicAdd(&g_arrive, 1u);
        s_last = (old == (unsigned int)(GRID - 1));
    }
    __syncthreads();
    if (!s_last) return;

    __threadfence();   // acquire all blocks' contributions
    const int i = threadIdx.x;
    float r = 0.0f;
    if (i < NC) {
        r = ((float)g_tp[i] + SMOOTH) / ((float)g_tt[i] + SMOOTH);
    }
    #pragma unroll
    for (int o = 16; o > 0; o >>= 1) r += __shfl_down_sync(0xffffffffu, r, o);
    if (lid == 0) s_red[wid] = r;
    __syncthreads();
    if (i == 0) {
        float s = 0.0f;
        #pragma unroll
        for (int w = 0; w < NWARP; w++) s += s_red[w];
        out[0] = 1.0f - s / (float)NC;
    }

    // Reset state for the next graph replay.
    if (i < NC) { g_tp[i] = 0; g_tt[i] = 0; }
    if (i == 0) g_arrive = 0u;
}

extern "C" void kernel_launch(void* const* d_in, const int* in_sizes, int n_in,
                              void* d_out, int out_size) {
    const float* inp = (const float*)d_in[0];
    const void*  tgt = d_in[1];
    float* out = (float*)d_out;

    recall_fused_kernel<<<GRID, TPB>>>(inp, tgt, out);
}